// round 12
// baseline (speedup 1.0000x reference)
#include <cuda_runtime.h>
#include <cuda_fp16.h>
#include <math.h>
#include <stdint.h>

// Problem dims (fixed by setup_inputs)
#define T_TOK 8192
#define D_DIM 2048
#define E_EXP 8
#define H_DIM 2048
#define C_CAP 2048
#define B_BATCH 4
#define S_SEQ 2048

// ---------------- device scratch (allocation-free) ----------------
__device__ int   g_e0[T_TOK], g_e1[T_TOK];
__device__ float g_g0[T_TOK], g_g1[T_TOK];
__device__ int   g_p0[T_TOK], g_p1[T_TOK];
__device__ int   g_src[E_EXP * C_CAP];
__device__ float g_w2sum[E_EXP * H_DIM];
__device__ float g_b2sum[E_EXP];
__device__ float g_rowsum[E_EXP * C_CAP];
// fp16 copies: x (written by gate), W1 transposed [e][h][d]
__device__ __align__(16) __half g_xh[(size_t)T_TOK * D_DIM];
__device__ __align__(16) __half g_w1h[(size_t)E_EXP * H_DIM * D_DIM];

// ---------------- helpers ----------------
__device__ __forceinline__ uint32_t smem_u32(const void* p) {
    uint32_t a;
    asm("{ .reg .u64 t; cvta.to.shared.u64 t, %1; cvt.u32.u64 %0, t; }" : "=r"(a) : "l"(p));
    return a;
}
#define LDM4(d, a) \
    asm volatile("ldmatrix.sync.aligned.m8n8.x4.shared.b16 {%0,%1,%2,%3}, [%4];" \
        : "=r"((d)[0]), "=r"((d)[1]), "=r"((d)[2]), "=r"((d)[3]) : "r"(a))
#define MMA(c, a, b) \
    asm volatile("mma.sync.aligned.m16n8k16.row.col.f32.f16.f16.f32 " \
        "{%0,%1,%2,%3},{%4,%5,%6,%7},{%8,%9},{%0,%1,%2,%3};" \
        : "+f"((c)[0]), "+f"((c)[1]), "+f"((c)[2]), "+f"((c)[3]) \
        : "r"((a)[0]), "r"((a)[1]), "r"((a)[2]), "r"((a)[3]), "r"((b)[0]), "r"((b)[1]))
#define CP16(dst, src) \
    asm volatile("cp.async.ca.shared.global [%0], [%1], 16;" :: "r"(dst), "l"(src) : "memory")
#define CP16Z(dst, src, n) \
    asm volatile("cp.async.ca.shared.global [%0], [%1], 16, %2;" :: "r"(dst), "l"(src), "r"(n) : "memory")
#define CP_COMMIT() asm volatile("cp.async.commit_group;" ::: "memory")
#define CP_WAIT2()  asm volatile("cp.async.wait_group 2;" ::: "memory")

// ================= K1a: gate (stream 0): exact fp32 routing + x->fp16 =================
// 4 tokens per block, 2 warps per token (split-K).
__global__ void __launch_bounds__(256) k_gate(const float* __restrict__ x,
                                              const float* __restrict__ Wg) {
    __shared__ float sm_g[4][2][8];
    const int tid = threadIdx.x, lane = tid & 31, wrp = tid >> 5;
    const int tok = blockIdx.x * 4 + (wrp >> 1);
    const int half = wrp & 1;
    const float* xr = x + (size_t)tok * D_DIM;
    __half* xhw = g_xh + (size_t)tok * D_DIM;
    float acc[8];
#pragma unroll
    for (int e = 0; e < 8; e++) acc[e] = 0.f;
#pragma unroll
    for (int i = 0; i < 8; i++) {
        const int k = (half * 256 + i * 32 + lane) * 4;
        float4 xv = *(const float4*)(xr + k);
        *(__half2*)(xhw + k)     = __floats2half2_rn(xv.x, xv.y);
        *(__half2*)(xhw + k + 2) = __floats2half2_rn(xv.z, xv.w);
        const float xs[4] = {xv.x, xv.y, xv.z, xv.w};
#pragma unroll
        for (int j = 0; j < 4; j++) {
            const float* wr = Wg + (size_t)(k + j) * 8;
            float4 w0 = *(const float4*)(wr);
            float4 w1v = *(const float4*)(wr + 4);
            acc[0] = fmaf(xs[j], w0.x, acc[0]);
            acc[1] = fmaf(xs[j], w0.y, acc[1]);
            acc[2] = fmaf(xs[j], w0.z, acc[2]);
            acc[3] = fmaf(xs[j], w0.w, acc[3]);
            acc[4] = fmaf(xs[j], w1v.x, acc[4]);
            acc[5] = fmaf(xs[j], w1v.y, acc[5]);
            acc[6] = fmaf(xs[j], w1v.z, acc[6]);
            acc[7] = fmaf(xs[j], w1v.w, acc[7]);
        }
    }
#pragma unroll
    for (int e = 0; e < 8; e++) {
#pragma unroll
        for (int off = 16; off > 0; off >>= 1)
            acc[e] += __shfl_xor_sync(0xffffffffu, acc[e], off);
    }
    if (lane == 0) {
#pragma unroll
        for (int e = 0; e < 8; e++) sm_g[wrp >> 1][half][e] = acc[e];
    }
    __syncthreads();
    if (wrp < 4 && lane == 0) {
        const int t2 = blockIdx.x * 4 + wrp;
        float l0 = -INFINITY, l1 = -INFINITY;
        int i0 = 0, i1 = 0;
#pragma unroll
        for (int e = 0; e < 8; e++) {
            float v = sm_g[wrp][0][e] + sm_g[wrp][1][e];
            if (v > l0) { l1 = l0; i1 = i0; l0 = v; i0 = e; }
            else if (v > l1) { l1 = v; i1 = e; }
        }
        float g0 = 1.f / (1.f + __expf(l1 - l0));
        g_e0[t2] = i0; g_e1[t2] = i1;
        g_g0[t2] = g0; g_g1[t2] = 1.f - g0;
    }
}

// ================= K1b: rest (stream 2): w1t + w2sum + b2sum =================
// Period 5: [4 w1t | 1 w2sum(8 rows)] x 2048 = 10240 blocks, + 1 b2sum block.
#define G_REST (10240 + 1)
__global__ void __launch_bounds__(256) k_rest(const float* __restrict__ W1,
                                              const float* __restrict__ W2,
                                              const float* __restrict__ b2) {
    __shared__ float tl[64][65];
    const int bid = blockIdx.x, tid = threadIdx.x;
    const int lane = tid & 31, wrp = tid >> 5;

    if (bid < 10240) {
        const int p = bid / 5, r = bid % 5;
        if (r < 4) {
            // ---- w1t: transpose W1 -> [e][h][d] fp16, 64x64 tile, vectorized ----
            const int w = p * 4 + r;               // 0..8191
            const int e = w >> 10;
            const int rem = w & 1023;
            const int h0 = (rem >> 5) * 64, d0 = (rem & 31) * 64;
            const int hx = (tid & 15) * 4;
            const int dB = tid >> 4;
#pragma unroll
            for (int i = 0; i < 4; i++) {
                const int dl = dB + i * 16;
                float4 v = *(const float4*)&W1[((size_t)e * D_DIM + d0 + dl) * H_DIM + h0 + hx];
                tl[dl][hx] = v.x; tl[dl][hx + 1] = v.y;
                tl[dl][hx + 2] = v.z; tl[dl][hx + 3] = v.w;
            }
            __syncthreads();
            const int dp = tid & 31;
            const int hB = tid >> 5;
#pragma unroll
            for (int i = 0; i < 8; i++) {
                const int hl = hB + i * 8;
                __half2 hv = __floats2half2_rn(tl[2 * dp][hl], tl[2 * dp + 1][hl]);
                *(__half2*)&g_w1h[((size_t)e * H_DIM + h0 + hl) * D_DIM + d0 + 2 * dp] = hv;
            }
        } else {
            // ---- w2sum: one warp per (e,h) row, 8 rows per block ----
            const int gw = p * 8 + wrp;            // < 16384
            const float* rr = W2 + (size_t)gw * D_DIM;
            float s = 0.f;
            for (int k = lane * 4; k < D_DIM; k += 128) {
                float4 vv = *(const float4*)(rr + k);
                s += (vv.x + vv.y) + (vv.z + vv.w);
            }
#pragma unroll
            for (int off = 16; off > 0; off >>= 1) s += __shfl_xor_sync(0xffffffffu, s, off);
            if (lane == 0) g_w2sum[gw] = s;
        }
    } else {
        // ---- b2sum ----
        if (wrp < 8) {
            float s = 0.f;
            for (int k = lane; k < D_DIM; k += 32) s += b2[(size_t)wrp * D_DIM + k];
#pragma unroll
            for (int off = 16; off > 0; off >>= 1) s += __shfl_xor_sync(0xffffffffu, s, off);
            if (lane == 0) g_b2sum[wrp] = s;
        }
    }
}

// ================= K2: dispatch scan (owns src/rowsum init; stream 0) =================
__global__ void __launch_bounds__(1024) k_scan() {
    __shared__ int wT0[32][8], wT1[32][8];
    __shared__ int wOff0[32][8], wOff1[32][8];
    __shared__ int shTot[8];
    const int tid = threadIdx.x, lane = tid & 31, w = tid >> 5;
    const int base = tid * 8;

    // init (moved here so stream-2 kernel never touches scan outputs)
#pragma unroll
    for (int i = 0; i < 16; i++) {
        int idx = tid + i * 1024;
        g_src[idx] = -1;
        g_rowsum[idx] = 0.f;
    }

    int4 a0 = *(const int4*)&g_e0[base];
    int4 a1 = *(const int4*)&g_e0[base + 4];
    int4 c0 = *(const int4*)&g_e1[base];
    int4 c1 = *(const int4*)&g_e1[base + 4];
    const int e0s[8] = {a0.x, a0.y, a0.z, a0.w, a1.x, a1.y, a1.z, a1.w};
    const int e1s[8] = {c0.x, c0.y, c0.z, c0.w, c1.x, c1.y, c1.z, c1.w};

    int cnt0[8], cnt1[8];
#pragma unroll
    for (int e = 0; e < 8; e++) { cnt0[e] = 0; cnt1[e] = 0; }
#pragma unroll
    for (int i = 0; i < 8; i++) { cnt0[e0s[i]]++; cnt1[e1s[i]]++; }

    int inc0[8], inc1[8];
#pragma unroll
    for (int e = 0; e < 8; e++) { inc0[e] = cnt0[e]; inc1[e] = cnt1[e]; }
#pragma unroll
    for (int off = 1; off < 32; off <<= 1) {
#pragma unroll
        for (int e = 0; e < 8; e++) {
            int v0 = __shfl_up_sync(0xffffffffu, inc0[e], off);
            int v1 = __shfl_up_sync(0xffffffffu, inc1[e], off);
            if (lane >= off) { inc0[e] += v0; inc1[e] += v1; }
        }
    }
    if (lane == 31) {
#pragma unroll
        for (int e = 0; e < 8; e++) { wT0[w][e] = inc0[e]; wT1[w][e] = inc1[e]; }
    }
    __syncthreads();
    if (w == 0) {
        int t0[8], t1[8], i0[8], i1[8];
#pragma unroll
        for (int e = 0; e < 8; e++) {
            t0[e] = wT0[lane][e]; t1[e] = wT1[lane][e];
            i0[e] = t0[e]; i1[e] = t1[e];
        }
#pragma unroll
        for (int off = 1; off < 32; off <<= 1) {
#pragma unroll
            for (int e = 0; e < 8; e++) {
                int v0 = __shfl_up_sync(0xffffffffu, i0[e], off);
                int v1 = __shfl_up_sync(0xffffffffu, i1[e], off);
                if (lane >= off) { i0[e] += v0; i1[e] += v1; }
            }
        }
#pragma unroll
        for (int e = 0; e < 8; e++) {
            wOff0[lane][e] = i0[e] - t0[e];
            wOff1[lane][e] = i1[e] - t1[e];
        }
        if (lane == 31) {
#pragma unroll
            for (int e = 0; e < 8; e++) shTot[e] = i0[e];
        }
    }
    __syncthreads();

    int run0[8], run1[8];
#pragma unroll
    for (int e = 0; e < 8; e++) {
        run0[e] = wOff0[w][e] + inc0[e] - cnt0[e];
        run1[e] = shTot[e] + wOff1[w][e] + inc1[e] - cnt1[e];
    }
#pragma unroll
    for (int i = 0; i < 8; i++) {
        int tok = base + i;
        int e = e0s[i];
        int pos = run0[e]++;
        if (pos < C_CAP) { g_p0[tok] = pos; g_src[e * C_CAP + pos] = tok; }
        else             { g_p0[tok] = -1; }
    }
#pragma unroll
    for (int i = 0; i < 8; i++) {
        int tok = base + i;
        int e = e1s[i];
        int pos = run1[e]++;
        if (pos < C_CAP) { g_p1[tok] = pos; g_src[e * C_CAP + pos] = tok; }
        else             { g_p1[tok] = -1; }
    }
}

// ================= K3: HMMA fused expert GEMM + relu*w2sum epilogue (unchanged) =================
#define STRIDE 80
#define OFF_A  0
#define OFF_B  10240
#define STAGE_SZ 30720
#define NSTAGE 4
#define OFF_W2 (STAGE_SZ * NSTAGE)
#define OFF_B1 (OFF_W2 + 1024)
#define SMEM_FFN (OFF_B1 + 1024)
#define NIT (D_DIM / 32)

__global__ void __launch_bounds__(256, 1) k_ffn(const float* __restrict__ b1) {
    extern __shared__ char smem[];
    const uint32_t sbase = smem_u32(smem);
    const int tid = threadIdx.x;
    const int lane = tid & 31, wid = tid >> 5;
    const int wm = wid >> 2, wn = wid & 3;
    const int e = blockIdx.z;
    const int row0 = blockIdx.y * 128;
    const int col0 = blockIdx.x * 256;

    float* sW2 = (float*)(smem + OFF_W2);
    float* sB1 = (float*)(smem + OFF_B1);
    sW2[tid] = g_w2sum[e * H_DIM + col0 + tid];
    sB1[tid] = b1[(size_t)e * H_DIM + col0 + tid];

    const int alr = tid >> 1;
    const int akseg = tid & 1;
    const int srcTok = g_src[e * C_CAP + row0 + alr];
    const int aPred = (srcTok >= 0) ? 16 : 0;
    const __half* aPtr = g_xh + (size_t)(srcTok >= 0 ? srcTok : 0) * D_DIM + akseg * 16;
    const int aByte = alr * STRIDE + akseg * 32;
    const int br0 = tid >> 1,         bk0 = tid & 1;
    const int br1 = (tid + 256) >> 1, bk1 = tid & 1;
    const __half* bPtr0 = g_w1h + (size_t)(e * H_DIM + col0 + br0) * D_DIM + bk0 * 16;
    const __half* bPtr1 = g_w1h + (size_t)(e * H_DIM + col0 + br1) * D_DIM + bk1 * 16;
    const int bByte0 = br0 * STRIDE + bk0 * 32;
    const int bByte1 = br1 * STRIDE + bk1 * 32;

    float acc[4][8][4];
#pragma unroll
    for (int i = 0; i < 4; i++)
#pragma unroll
        for (int j = 0; j < 8; j++)
#pragma unroll
            for (int q = 0; q < 4; q++) acc[i][j][q] = 0.f;

    auto issue = [&](int it, int st) {
        const uint32_t sb = sbase + st * STAGE_SZ;
        const int co = it * 32;
        CP16Z(sb + OFF_A + aByte,      aPtr + co,     aPred);
        CP16Z(sb + OFF_A + aByte + 16, aPtr + co + 8, aPred);
        CP16(sb + OFF_B + bByte0,      bPtr0 + co);
        CP16(sb + OFF_B + bByte0 + 16, bPtr0 + co + 8);
        CP16(sb + OFF_B + bByte1,      bPtr1 + co);
        CP16(sb + OFF_B + bByte1 + 16, bPtr1 + co + 8);
    };

    issue(0, 0); CP_COMMIT();
    issue(1, 1); CP_COMMIT();
    issue(2, 2); CP_COMMIT();

    const uint32_t aFragOff = (wm * 64 + (lane & 15)) * STRIDE + ((lane >> 4) << 4);
    const uint32_t bFragOff = (wn * 64 + (lane & 15)) * STRIDE + ((lane >> 4) << 4);

    for (int it = 0; it < NIT; it++) {
        const int st = it & (NSTAGE - 1);
        CP_WAIT2();
        __syncthreads();
        if (it + 3 < NIT) issue(it + 3, (it + 3) & (NSTAGE - 1));
        CP_COMMIT();

        const uint32_t aB = sbase + st * STAGE_SZ + OFF_A + aFragOff;
        const uint32_t bB = sbase + st * STAGE_SZ + OFF_B + bFragOff;
#pragma unroll
        for (int kh = 0; kh < 2; kh++) {
            uint32_t a[4][4], b[8][2];
#pragma unroll
            for (int ma = 0; ma < 4; ma++)
                LDM4(a[ma], aB + ma * (16 * STRIDE) + kh * 32);
#pragma unroll
            for (int np = 0; np < 4; np++) {
                uint32_t tr[4];
                LDM4(tr, bB + np * (16 * STRIDE) + kh * 32);
                b[np * 2][0] = tr[0];     b[np * 2][1] = tr[2];
                b[np * 2 + 1][0] = tr[1]; b[np * 2 + 1][1] = tr[3];
            }
#pragma unroll
            for (int ma = 0; ma < 4; ma++)
#pragma unroll
                for (int na = 0; na < 8; na++)
                    MMA(acc[ma][na], a[ma], b[na]);
        }
    }

#pragma unroll
    for (int ma = 0; ma < 4; ma++) {
        float s0 = 0.f, s1 = 0.f;
#pragma unroll
        for (int na = 0; na < 8; na++) {
            int cb = wn * 64 + na * 8 + (lane & 3) * 2;
            float w0 = sW2[cb], w1v = sW2[cb + 1];
            float bb0 = sB1[cb], bb1 = sB1[cb + 1];
            s0 += fmaxf(acc[ma][na][0] + bb0, 0.f) * w0
                + fmaxf(acc[ma][na][1] + bb1, 0.f) * w1v;
            s1 += fmaxf(acc[ma][na][2] + bb0, 0.f) * w0
                + fmaxf(acc[ma][na][3] + bb1, 0.f) * w1v;
        }
        s0 += __shfl_xor_sync(0xffffffffu, s0, 1);
        s0 += __shfl_xor_sync(0xffffffffu, s0, 2);
        s1 += __shfl_xor_sync(0xffffffffu, s1, 1);
        s1 += __shfl_xor_sync(0xffffffffu, s1, 2);
        if ((lane & 3) == 0) {
            int r = row0 + wm * 64 + ma * 16 + (lane >> 2);
            atomicAdd(&g_rowsum[e * C_CAP + r], s0);
            atomicAdd(&g_rowsum[e * C_CAP + r + 8], s1);
        }
    }
}

// ================= K4: fused combine + log_softmax (1024 threads) =================
__global__ void __launch_bounds__(1024) k_out(float* __restrict__ out) {
    __shared__ float sy[S_SEQ];
    __shared__ float red[1024];
    const int b = blockIdx.x, tid = threadIdx.x;

    for (int s = tid; s < S_SEQ; s += 1024) {
        int t = b * S_SEQ + s;
        float y = 0.f;
        int p0 = g_p0[t];
        if (p0 >= 0) {
            int e = g_e0[t];
            y += g_g0[t] * (g_rowsum[e * C_CAP + p0] + g_b2sum[e]);
        }
        int p1 = g_p1[t];
        if (p1 >= 0) {
            int e = g_e1[t];
            y += g_g1[t] * (g_rowsum[e * C_CAP + p1] + g_b2sum[e]);
        }
        sy[s] = y;
    }
    __syncthreads();

    float m = fmaxf(sy[tid], sy[tid + 1024]);
    red[tid] = m; __syncthreads();
    for (int off = 512; off > 0; off >>= 1) {
        if (tid < off) red[tid] = fmaxf(red[tid], red[tid + off]);
        __syncthreads();
    }
    m = red[0]; __syncthreads();

    float sum = expf(sy[tid] - m) + expf(sy[tid + 1024] - m);
    red[tid] = sum; __syncthreads();
    for (int off = 512; off > 0; off >>= 1) {
        if (tid < off) red[tid] += red[tid + off];
        __syncthreads();
    }
    float lse = m + logf(red[0]);

    out[(size_t)b * S_SEQ + tid] = sy[tid] - lse;
    out[(size_t)b * S_SEQ + tid + 1024] = sy[tid + 1024] - lse;
}

// ---------------- launch: fork-join overlap of gate/scan with w1t/w2sum ----------------
extern "C" void kernel_launch(void* const* d_in, const int* in_sizes, int n_in,
                              void* d_out, int out_size) {
    const float* x  = (const float*)d_in[0];
    const float* Wg = (const float*)d_in[1];
    const float* W1 = (const float*)d_in[2];
    const float* b1 = (const float*)d_in[3];
    const float* W2 = (const float*)d_in[4];
    const float* b2 = (const float*)d_in[5];
    float* out = (float*)d_out;

    cudaFuncSetAttribute(k_ffn, cudaFuncAttributeMaxDynamicSharedMemorySize, SMEM_FFN);

    cudaStream_t s2 = 0;
    cudaEvent_t ev0 = 0, ev2 = 0;
    bool forked = false;
    if (cudaStreamCreateWithFlags(&s2, cudaStreamNonBlocking) == cudaSuccess) {
        if (cudaEventCreateWithFlags(&ev0, cudaEventDisableTiming) == cudaSuccess &&
            cudaEventCreateWithFlags(&ev2, cudaEventDisableTiming) == cudaSuccess) {
            forked = true;
        }
    }

    if (forked) {
        // fork: s2 branches off the main (captured) stream
        cudaEventRecord(ev0, 0);
        cudaStreamWaitEvent(s2, ev0, 0);
        k_rest<<<G_REST, 256, 0, s2>>>(W1, W2, b2);   // w1t + w2sum + b2sum
        k_gate<<<T_TOK / 4, 256>>>(x, Wg);            // main stream
        k_scan<<<1, 1024>>>();                        // main stream (owns init)
        // join
        cudaEventRecord(ev2, s2);
        cudaStreamWaitEvent(0, ev2, 0);
    } else {
        // serial fallback
        k_rest<<<G_REST, 256>>>(W1, W2, b2);
        k_gate<<<T_TOK / 4, 256>>>(x, Wg);
        k_scan<<<1, 1024>>>();
    }

    k_ffn<<<dim3(H_DIM / 256, C_CAP / 128, E_EXP), 256, SMEM_FFN>>>(b1);
    k_out<<<B_BATCH, 1024>>>(out);
}

// round 13
// speedup vs baseline: 1.0257x; 1.0257x over previous
#include <cuda_runtime.h>
#include <cuda_fp16.h>
#include <math.h>
#include <stdint.h>

// Problem dims (fixed by setup_inputs)
#define T_TOK 8192
#define D_DIM 2048
#define E_EXP 8
#define H_DIM 2048
#define C_CAP 2048
#define B_BATCH 4
#define S_SEQ 2048

// ---------------- device scratch (allocation-free) ----------------
__device__ int   g_e0[T_TOK], g_e1[T_TOK];
__device__ float g_g0[T_TOK], g_g1[T_TOK];
__device__ int   g_p0[T_TOK], g_p1[T_TOK];
__device__ int   g_src[E_EXP * C_CAP];
__device__ float g_w2sum[E_EXP * H_DIM];
__device__ float g_b2sum[E_EXP];
__device__ float g_rowsum[E_EXP * C_CAP];
// fp16 copies: x (written by gate), W1 transposed [e][h][d]
__device__ __align__(16) __half g_xh[(size_t)T_TOK * D_DIM];
__device__ __align__(16) __half g_w1h[(size_t)E_EXP * H_DIM * D_DIM];

// ---------------- helpers ----------------
__device__ __forceinline__ uint32_t smem_u32(const void* p) {
    uint32_t a;
    asm("{ .reg .u64 t; cvta.to.shared.u64 t, %1; cvt.u32.u64 %0, t; }" : "=r"(a) : "l"(p));
    return a;
}
#define LDM4(d, a) \
    asm volatile("ldmatrix.sync.aligned.m8n8.x4.shared.b16 {%0,%1,%2,%3}, [%4];" \
        : "=r"((d)[0]), "=r"((d)[1]), "=r"((d)[2]), "=r"((d)[3]) : "r"(a))
// c += A * {b0,b1}  (direct B regs, no repack)
#define MMA2(c, a, b0, b1) \
    asm volatile("mma.sync.aligned.m16n8k16.row.col.f32.f16.f16.f32 " \
        "{%0,%1,%2,%3},{%4,%5,%6,%7},{%8,%9},{%0,%1,%2,%3};" \
        : "+f"((c)[0]), "+f"((c)[1]), "+f"((c)[2]), "+f"((c)[3]) \
        : "r"((a)[0]), "r"((a)[1]), "r"((a)[2]), "r"((a)[3]), "r"(b0), "r"(b1))
#define CP16(dst, src) \
    asm volatile("cp.async.ca.shared.global [%0], [%1], 16;" :: "r"(dst), "l"(src) : "memory")
#define CP16Z(dst, src, n) \
    asm volatile("cp.async.ca.shared.global [%0], [%1], 16, %2;" :: "r"(dst), "l"(src), "r"(n) : "memory")
#define CP_COMMIT() asm volatile("cp.async.commit_group;" ::: "memory")
#define CP_WAIT2()  asm volatile("cp.async.wait_group 2;" ::: "memory")

// ================= K1: fused prep (serial, period 6) =================
// [4 w1t | 1 gate(4 tokens, 2 warps each) | 1 w2sum(8 rows)] x 2048, + 64 init + 1 b2sum.
#define GB_PERIOD 6
#define G_MAIN (2048 * GB_PERIOD)
#define G_INIT 64
#define G_PREP (G_MAIN + G_INIT + 1)

__global__ void __launch_bounds__(256) k_prep(const float* __restrict__ x,
                                              const float* __restrict__ Wg,
                                              const float* __restrict__ W1,
                                              const float* __restrict__ W2,
                                              const float* __restrict__ b2) {
    __shared__ float tl[64][65];
    __shared__ float sm_g[4][2][8];
    const int bid = blockIdx.x, tid = threadIdx.x;
    const int lane = tid & 31, wrp = tid >> 5;

    if (bid < G_MAIN) {
        const int p = bid / GB_PERIOD, r = bid % GB_PERIOD;
        if (r < 4) {
            const int w = p * 4 + r;
            const int e = w >> 10;
            const int rem = w & 1023;
            const int h0 = (rem >> 5) * 64, d0 = (rem & 31) * 64;
            const int hx = (tid & 15) * 4;
            const int dB = tid >> 4;
#pragma unroll
            for (int i = 0; i < 4; i++) {
                const int dl = dB + i * 16;
                float4 v = *(const float4*)&W1[((size_t)e * D_DIM + d0 + dl) * H_DIM + h0 + hx];
                tl[dl][hx] = v.x; tl[dl][hx + 1] = v.y;
                tl[dl][hx + 2] = v.z; tl[dl][hx + 3] = v.w;
            }
            __syncthreads();
            const int dp = tid & 31;
            const int hB = tid >> 5;
#pragma unroll
            for (int i = 0; i < 8; i++) {
                const int hl = hB + i * 8;
                __half2 hv = __floats2half2_rn(tl[2 * dp][hl], tl[2 * dp + 1][hl]);
                *(__half2*)&g_w1h[((size_t)e * H_DIM + h0 + hl) * D_DIM + d0 + 2 * dp] = hv;
            }
        } else if (r == 4) {
            const int tok = p * 4 + (wrp >> 1);
            const int half = wrp & 1;
            const float* xr = x + (size_t)tok * D_DIM;
            __half* xhw = g_xh + (size_t)tok * D_DIM;
            float acc[8];
#pragma unroll
            for (int e = 0; e < 8; e++) acc[e] = 0.f;
#pragma unroll
            for (int i = 0; i < 8; i++) {
                const int k = (half * 256 + i * 32 + lane) * 4;
                float4 xv = *(const float4*)(xr + k);
                *(__half2*)(xhw + k)     = __floats2half2_rn(xv.x, xv.y);
                *(__half2*)(xhw + k + 2) = __floats2half2_rn(xv.z, xv.w);
                const float xs[4] = {xv.x, xv.y, xv.z, xv.w};
#pragma unroll
                for (int j = 0; j < 4; j++) {
                    const float* wr = Wg + (size_t)(k + j) * 8;
                    float4 w0 = *(const float4*)(wr);
                    float4 w1v = *(const float4*)(wr + 4);
                    acc[0] = fmaf(xs[j], w0.x, acc[0]);
                    acc[1] = fmaf(xs[j], w0.y, acc[1]);
                    acc[2] = fmaf(xs[j], w0.z, acc[2]);
                    acc[3] = fmaf(xs[j], w0.w, acc[3]);
                    acc[4] = fmaf(xs[j], w1v.x, acc[4]);
                    acc[5] = fmaf(xs[j], w1v.y, acc[5]);
                    acc[6] = fmaf(xs[j], w1v.z, acc[6]);
                    acc[7] = fmaf(xs[j], w1v.w, acc[7]);
                }
            }
#pragma unroll
            for (int e = 0; e < 8; e++) {
#pragma unroll
                for (int off = 16; off > 0; off >>= 1)
                    acc[e] += __shfl_xor_sync(0xffffffffu, acc[e], off);
            }
            if (lane == 0) {
#pragma unroll
                for (int e = 0; e < 8; e++) sm_g[wrp >> 1][half][e] = acc[e];
            }
            __syncthreads();
            if (wrp < 4 && lane == 0) {
                const int t2 = p * 4 + wrp;
                float l0 = -INFINITY, l1 = -INFINITY;
                int i0 = 0, i1 = 0;
#pragma unroll
                for (int e = 0; e < 8; e++) {
                    float v = sm_g[wrp][0][e] + sm_g[wrp][1][e];
                    if (v > l0) { l1 = l0; i1 = i0; l0 = v; i0 = e; }
                    else if (v > l1) { l1 = v; i1 = e; }
                }
                float g0 = 1.f / (1.f + __expf(l1 - l0));
                g_e0[t2] = i0; g_e1[t2] = i1;
                g_g0[t2] = g0; g_g1[t2] = 1.f - g0;
            }
        } else {
            const int gw = p * 8 + wrp;
            const float* rr = W2 + (size_t)gw * D_DIM;
            float s = 0.f;
            for (int k = lane * 4; k < D_DIM; k += 128) {
                float4 vv = *(const float4*)(rr + k);
                s += (vv.x + vv.y) + (vv.z + vv.w);
            }
#pragma unroll
            for (int off = 16; off > 0; off >>= 1) s += __shfl_xor_sync(0xffffffffu, s, off);
            if (lane == 0) g_w2sum[gw] = s;
        }
    } else if (bid < G_MAIN + G_INIT) {
        int i = (bid - G_MAIN) * 256 + tid;
        g_src[i] = -1;
        g_rowsum[i] = 0.f;
    } else {
        if (wrp < 8) {
            float s = 0.f;
            for (int k = lane; k < D_DIM; k += 32) s += b2[(size_t)wrp * D_DIM + k];
#pragma unroll
            for (int off = 16; off > 0; off >>= 1) s += __shfl_xor_sync(0xffffffffu, s, off);
            if (lane == 0) g_b2sum[wrp] = s;
        }
    }
}

// ================= K2: dispatch scan (1024 threads) =================
__global__ void __launch_bounds__(1024) k_scan() {
    __shared__ int wT0[32][8], wT1[32][8];
    __shared__ int wOff0[32][8], wOff1[32][8];
    __shared__ int shTot[8];
    const int tid = threadIdx.x, lane = tid & 31, w = tid >> 5;
    const int base = tid * 8;

    int4 a0 = *(const int4*)&g_e0[base];
    int4 a1 = *(const int4*)&g_e0[base + 4];
    int4 c0 = *(const int4*)&g_e1[base];
    int4 c1 = *(const int4*)&g_e1[base + 4];
    const int e0s[8] = {a0.x, a0.y, a0.z, a0.w, a1.x, a1.y, a1.z, a1.w};
    const int e1s[8] = {c0.x, c0.y, c0.z, c0.w, c1.x, c1.y, c1.z, c1.w};

    int cnt0[8], cnt1[8];
#pragma unroll
    for (int e = 0; e < 8; e++) { cnt0[e] = 0; cnt1[e] = 0; }
#pragma unroll
    for (int i = 0; i < 8; i++) { cnt0[e0s[i]]++; cnt1[e1s[i]]++; }

    int inc0[8], inc1[8];
#pragma unroll
    for (int e = 0; e < 8; e++) { inc0[e] = cnt0[e]; inc1[e] = cnt1[e]; }
#pragma unroll
    for (int off = 1; off < 32; off <<= 1) {
#pragma unroll
        for (int e = 0; e < 8; e++) {
            int v0 = __shfl_up_sync(0xffffffffu, inc0[e], off);
            int v1 = __shfl_up_sync(0xffffffffu, inc1[e], off);
            if (lane >= off) { inc0[e] += v0; inc1[e] += v1; }
        }
    }
    if (lane == 31) {
#pragma unroll
        for (int e = 0; e < 8; e++) { wT0[w][e] = inc0[e]; wT1[w][e] = inc1[e]; }
    }
    __syncthreads();
    if (w == 0) {
        int t0[8], t1[8], i0[8], i1[8];
#pragma unroll
        for (int e = 0; e < 8; e++) {
            t0[e] = wT0[lane][e]; t1[e] = wT1[lane][e];
            i0[e] = t0[e]; i1[e] = t1[e];
        }
#pragma unroll
        for (int off = 1; off < 32; off <<= 1) {
#pragma unroll
            for (int e = 0; e < 8; e++) {
                int v0 = __shfl_up_sync(0xffffffffu, i0[e], off);
                int v1 = __shfl_up_sync(0xffffffffu, i1[e], off);
                if (lane >= off) { i0[e] += v0; i1[e] += v1; }
            }
        }
#pragma unroll
        for (int e = 0; e < 8; e++) {
            wOff0[lane][e] = i0[e] - t0[e];
            wOff1[lane][e] = i1[e] - t1[e];
        }
        if (lane == 31) {
#pragma unroll
            for (int e = 0; e < 8; e++) shTot[e] = i0[e];
        }
    }
    __syncthreads();

    int run0[8], run1[8];
#pragma unroll
    for (int e = 0; e < 8; e++) {
        run0[e] = wOff0[w][e] + inc0[e] - cnt0[e];
        run1[e] = shTot[e] + wOff1[w][e] + inc1[e] - cnt1[e];
    }
#pragma unroll
    for (int i = 0; i < 8; i++) {
        int tok = base + i;
        int e = e0s[i];
        int pos = run0[e]++;
        if (pos < C_CAP) { g_p0[tok] = pos; g_src[e * C_CAP + pos] = tok; }
        else             { g_p0[tok] = -1; }
    }
#pragma unroll
    for (int i = 0; i < 8; i++) {
        int tok = base + i;
        int e = e1s[i];
        int pos = run1[e]++;
        if (pos < C_CAP) { g_p1[tok] = pos; g_src[e * C_CAP + pos] = tok; }
        else             { g_p1[tok] = -1; }
    }
}

// ================= K3: HMMA fused expert GEMM + relu*w2sum epilogue =================
// Tile M=128 x N=256, BK=32, 8 warps (2x4, warp tile 64x64), single fp16 pass.
// Restructured: B fragments consumed directly, stage addresses constant-folded (x4 unroll).
#define STRIDE 80
#define OFF_A  0
#define OFF_B  10240
#define STAGE_SZ 30720
#define NSTAGE 4
#define OFF_W2 (STAGE_SZ * NSTAGE)
#define OFF_B1 (OFF_W2 + 1024)
#define SMEM_FFN (OFF_B1 + 1024)
#define NIT (D_DIM / 32)

__global__ void __launch_bounds__(256, 1) k_ffn(const float* __restrict__ b1) {
    extern __shared__ char smem[];
    const uint32_t sbase = smem_u32(smem);
    const int tid = threadIdx.x;
    const int lane = tid & 31, wid = tid >> 5;
    const int wm = wid >> 2, wn = wid & 3;
    const int e = blockIdx.z;
    const int row0 = blockIdx.y * 128;
    const int col0 = blockIdx.x * 256;

    float* sW2 = (float*)(smem + OFF_W2);
    float* sB1 = (float*)(smem + OFF_B1);
    sW2[tid] = g_w2sum[e * H_DIM + col0 + tid];
    sB1[tid] = b1[(size_t)e * H_DIM + col0 + tid];

    const int alr = tid >> 1;
    const int akseg = tid & 1;
    const int srcTok = g_src[e * C_CAP + row0 + alr];
    const int aPred = (srcTok >= 0) ? 16 : 0;
    const __half* aPtr = g_xh + (size_t)(srcTok >= 0 ? srcTok : 0) * D_DIM + akseg * 16;
    const int aByte = alr * STRIDE + akseg * 32;
    const int br0 = tid >> 1,         bk0 = tid & 1;
    const int br1 = (tid + 256) >> 1, bk1 = tid & 1;
    const __half* bPtr0 = g_w1h + (size_t)(e * H_DIM + col0 + br0) * D_DIM + bk0 * 16;
    const __half* bPtr1 = g_w1h + (size_t)(e * H_DIM + col0 + br1) * D_DIM + bk1 * 16;
    const int bByte0 = br0 * STRIDE + bk0 * 32;
    const int bByte1 = br1 * STRIDE + bk1 * 32;

    float acc[4][8][4];
#pragma unroll
    for (int i = 0; i < 4; i++)
#pragma unroll
        for (int j = 0; j < 8; j++)
#pragma unroll
            for (int q = 0; q < 4; q++) acc[i][j][q] = 0.f;

    auto issue = [&](int it, int st) {
        const uint32_t sb = sbase + st * STAGE_SZ;
        const int co = it * 32;
        CP16Z(sb + OFF_A + aByte,      aPtr + co,     aPred);
        CP16Z(sb + OFF_A + aByte + 16, aPtr + co + 8, aPred);
        CP16(sb + OFF_B + bByte0,      bPtr0 + co);
        CP16(sb + OFF_B + bByte0 + 16, bPtr0 + co + 8);
        CP16(sb + OFF_B + bByte1,      bPtr1 + co);
        CP16(sb + OFF_B + bByte1 + 16, bPtr1 + co + 8);
    };

    issue(0, 0); CP_COMMIT();
    issue(1, 1); CP_COMMIT();
    issue(2, 2); CP_COMMIT();

    // precomputed per-stage fragment base addresses (constant-folded in x4 unroll)
    const uint32_t aFragOff = (wm * 64 + (lane & 15)) * STRIDE + ((lane >> 4) << 4);
    const uint32_t bFragOff = (wn * 64 + (lane & 15)) * STRIDE + ((lane >> 4) << 4);
    uint32_t aStage[NSTAGE], bStage[NSTAGE];
#pragma unroll
    for (int s = 0; s < NSTAGE; s++) {
        aStage[s] = sbase + s * STAGE_SZ + OFF_A + aFragOff;
        bStage[s] = sbase + s * STAGE_SZ + OFF_B + bFragOff;
    }

    for (int it4 = 0; it4 < NIT / 4; it4++) {
#pragma unroll
        for (int s = 0; s < 4; s++) {
            const int it = it4 * 4 + s;
            CP_WAIT2();
            __syncthreads();
            if (it + 3 < NIT) issue(it + 3, (s + 3) & 3);
            CP_COMMIT();

            const uint32_t aB = aStage[s];
            const uint32_t bB = bStage[s];
#pragma unroll
            for (int kh = 0; kh < 2; kh++) {
                uint32_t a[4][4];
#pragma unroll
                for (int ma = 0; ma < 4; ma++)
                    LDM4(a[ma], aB + ma * (16 * STRIDE) + kh * 32);
#pragma unroll
                for (int np = 0; np < 4; np++) {
                    uint32_t tr[4];
                    LDM4(tr, bB + np * (16 * STRIDE) + kh * 32);
#pragma unroll
                    for (int ma = 0; ma < 4; ma++) {
                        MMA2(acc[ma][np * 2],     a[ma], tr[0], tr[2]);
                        MMA2(acc[ma][np * 2 + 1], a[ma], tr[1], tr[3]);
                    }
                }
            }
        }
    }

    // ---- epilogue: relu(z + b1) * w2sum, reduce over N, one atomic per row ----
#pragma unroll
    for (int ma = 0; ma < 4; ma++) {
        float s0 = 0.f, s1 = 0.f;
#pragma unroll
        for (int na = 0; na < 8; na++) {
            int cb = wn * 64 + na * 8 + (lane & 3) * 2;
            float w0 = sW2[cb], w1v = sW2[cb + 1];
            float bb0 = sB1[cb], bb1 = sB1[cb + 1];
            s0 += fmaxf(acc[ma][na][0] + bb0, 0.f) * w0
                + fmaxf(acc[ma][na][1] + bb1, 0.f) * w1v;
            s1 += fmaxf(acc[ma][na][2] + bb0, 0.f) * w0
                + fmaxf(acc[ma][na][3] + bb1, 0.f) * w1v;
        }
        s0 += __shfl_xor_sync(0xffffffffu, s0, 1);
        s0 += __shfl_xor_sync(0xffffffffu, s0, 2);
        s1 += __shfl_xor_sync(0xffffffffu, s1, 1);
        s1 += __shfl_xor_sync(0xffffffffu, s1, 2);
        if ((lane & 3) == 0) {
            int r = row0 + wm * 64 + ma * 16 + (lane >> 2);
            atomicAdd(&g_rowsum[e * C_CAP + r], s0);
            atomicAdd(&g_rowsum[e * C_CAP + r + 8], s1);
        }
    }
}

// ================= K4: fused combine + log_softmax (1024 threads) =================
__global__ void __launch_bounds__(1024) k_out(float* __restrict__ out) {
    __shared__ float sy[S_SEQ];
    __shared__ float red[1024];
    const int b = blockIdx.x, tid = threadIdx.x;

    for (int s = tid; s < S_SEQ; s += 1024) {
        int t = b * S_SEQ + s;
        float y = 0.f;
        int p0 = g_p0[t];
        if (p0 >= 0) {
            int e = g_e0[t];
            y += g_g0[t] * (g_rowsum[e * C_CAP + p0] + g_b2sum[e]);
        }
        int p1 = g_p1[t];
        if (p1 >= 0) {
            int e = g_e1[t];
            y += g_g1[t] * (g_rowsum[e * C_CAP + p1] + g_b2sum[e]);
        }
        sy[s] = y;
    }
    __syncthreads();

    float m = fmaxf(sy[tid], sy[tid + 1024]);
    red[tid] = m; __syncthreads();
    for (int off = 512; off > 0; off >>= 1) {
        if (tid < off) red[tid] = fmaxf(red[tid], red[tid + off]);
        __syncthreads();
    }
    m = red[0]; __syncthreads();

    float sum = expf(sy[tid] - m) + expf(sy[tid + 1024] - m);
    red[tid] = sum; __syncthreads();
    for (int off = 512; off > 0; off >>= 1) {
        if (tid < off) red[tid] += red[tid + off];
        __syncthreads();
    }
    float lse = m + logf(red[0]);

    out[(size_t)b * S_SEQ + tid] = sy[tid] - lse;
    out[(size_t)b * S_SEQ + tid + 1024] = sy[tid + 1024] - lse;
}

// ---------------- launch (serial — fork-join regressed in R12) ----------------
extern "C" void kernel_launch(void* const* d_in, const int* in_sizes, int n_in,
                              void* d_out, int out_size) {
    const float* x  = (const float*)d_in[0];
    const float* Wg = (const float*)d_in[1];
    const float* W1 = (const float*)d_in[2];
    const float* b1 = (const float*)d_in[3];
    const float* W2 = (const float*)d_in[4];
    const float* b2 = (const float*)d_in[5];
    float* out = (float*)d_out;

    cudaFuncSetAttribute(k_ffn, cudaFuncAttributeMaxDynamicSharedMemorySize, SMEM_FFN);

    k_prep<<<G_PREP, 256>>>(x, Wg, W1, W2, b2);
    k_scan<<<1, 1024>>>();
    k_ffn<<<dim3(H_DIM / 256, C_CAP / 128, E_EXP), 256, SMEM_FFN>>>(b1);
    k_out<<<B_BATCH, 1024>>>(out);
}

// round 14
// speedup vs baseline: 1.0901x; 1.0628x over previous
#include <cuda_runtime.h>
#include <cuda_fp16.h>
#include <math.h>
#include <stdint.h>

// Problem dims (fixed by setup_inputs)
#define T_TOK 8192
#define D_DIM 2048
#define E_EXP 8
#define H_DIM 2048
#define C_CAP 2048
#define B_BATCH 4
#define S_SEQ 2048

// ---------------- device scratch (allocation-free) ----------------
__device__ int   g_e0[T_TOK], g_e1[T_TOK];
__device__ float g_g0[T_TOK], g_g1[T_TOK];
__device__ int   g_p0[T_TOK], g_p1[T_TOK];
__device__ int   g_src[E_EXP * C_CAP];
__device__ float g_w2sum[E_EXP * H_DIM];
__device__ float g_b2sum[E_EXP];
__device__ float g_rowsum[E_EXP * C_CAP];
// fp16 copies: x (written by gate), W1 transposed [e][h][d]
__device__ __align__(16) __half g_xh[(size_t)T_TOK * D_DIM];
__device__ __align__(16) __half g_w1h[(size_t)E_EXP * H_DIM * D_DIM];

// ---------------- helpers ----------------
__device__ __forceinline__ uint32_t smem_u32(const void* p) {
    uint32_t a;
    asm("{ .reg .u64 t; cvta.to.shared.u64 t, %1; cvt.u32.u64 %0, t; }" : "=r"(a) : "l"(p));
    return a;
}
#define LDM4(d, a) \
    asm volatile("ldmatrix.sync.aligned.m8n8.x4.shared.b16 {%0,%1,%2,%3}, [%4];" \
        : "=r"((d)[0]), "=r"((d)[1]), "=r"((d)[2]), "=r"((d)[3]) : "r"(a))
// c += A * {b0,b1}  (direct B regs, no repack)
#define MMA2(c, a, b0, b1) \
    asm volatile("mma.sync.aligned.m16n8k16.row.col.f32.f16.f16.f32 " \
        "{%0,%1,%2,%3},{%4,%5,%6,%7},{%8,%9},{%0,%1,%2,%3};" \
        : "+f"((c)[0]), "+f"((c)[1]), "+f"((c)[2]), "+f"((c)[3]) \
        : "r"((a)[0]), "r"((a)[1]), "r"((a)[2]), "r"((a)[3]), "r"(b0), "r"(b1))
#define CP16(dst, src) \
    asm volatile("cp.async.ca.shared.global [%0], [%1], 16;" :: "r"(dst), "l"(src) : "memory")
#define CP16Z(dst, src, n) \
    asm volatile("cp.async.ca.shared.global [%0], [%1], 16, %2;" :: "r"(dst), "l"(src), "r"(n) : "memory")
#define CP_COMMIT() asm volatile("cp.async.commit_group;" ::: "memory")
#define CP_WAIT2()  asm volatile("cp.async.wait_group 2;" ::: "memory")

// ================= K1: fused prep (serial, period 6) =================
#define GB_PERIOD 6
#define G_MAIN (2048 * GB_PERIOD)
#define G_INIT 64
#define G_PREP (G_MAIN + G_INIT + 1)

__global__ void __launch_bounds__(256) k_prep(const float* __restrict__ x,
                                              const float* __restrict__ Wg,
                                              const float* __restrict__ W1,
                                              const float* __restrict__ W2,
                                              const float* __restrict__ b2) {
    __shared__ float tl[64][65];
    __shared__ float sm_g[4][2][8];
    const int bid = blockIdx.x, tid = threadIdx.x;
    const int lane = tid & 31, wrp = tid >> 5;

    if (bid < G_MAIN) {
        const int p = bid / GB_PERIOD, r = bid % GB_PERIOD;
        if (r < 4) {
            const int w = p * 4 + r;
            const int e = w >> 10;
            const int rem = w & 1023;
            const int h0 = (rem >> 5) * 64, d0 = (rem & 31) * 64;
            const int hx = (tid & 15) * 4;
            const int dB = tid >> 4;
#pragma unroll
            for (int i = 0; i < 4; i++) {
                const int dl = dB + i * 16;
                float4 v = *(const float4*)&W1[((size_t)e * D_DIM + d0 + dl) * H_DIM + h0 + hx];
                tl[dl][hx] = v.x; tl[dl][hx + 1] = v.y;
                tl[dl][hx + 2] = v.z; tl[dl][hx + 3] = v.w;
            }
            __syncthreads();
            const int dp = tid & 31;
            const int hB = tid >> 5;
#pragma unroll
            for (int i = 0; i < 8; i++) {
                const int hl = hB + i * 8;
                __half2 hv = __floats2half2_rn(tl[2 * dp][hl], tl[2 * dp + 1][hl]);
                *(__half2*)&g_w1h[((size_t)e * H_DIM + h0 + hl) * D_DIM + d0 + 2 * dp] = hv;
            }
        } else if (r == 4) {
            const int tok = p * 4 + (wrp >> 1);
            const int half = wrp & 1;
            const float* xr = x + (size_t)tok * D_DIM;
            __half* xhw = g_xh + (size_t)tok * D_DIM;
            float acc[8];
#pragma unroll
            for (int e = 0; e < 8; e++) acc[e] = 0.f;
#pragma unroll
            for (int i = 0; i < 8; i++) {
                const int k = (half * 256 + i * 32 + lane) * 4;
                float4 xv = *(const float4*)(xr + k);
                *(__half2*)(xhw + k)     = __floats2half2_rn(xv.x, xv.y);
                *(__half2*)(xhw + k + 2) = __floats2half2_rn(xv.z, xv.w);
                const float xs[4] = {xv.x, xv.y, xv.z, xv.w};
#pragma unroll
                for (int j = 0; j < 4; j++) {
                    const float* wr = Wg + (size_t)(k + j) * 8;
                    float4 w0 = *(const float4*)(wr);
                    float4 w1v = *(const float4*)(wr + 4);
                    acc[0] = fmaf(xs[j], w0.x, acc[0]);
                    acc[1] = fmaf(xs[j], w0.y, acc[1]);
                    acc[2] = fmaf(xs[j], w0.z, acc[2]);
                    acc[3] = fmaf(xs[j], w0.w, acc[3]);
                    acc[4] = fmaf(xs[j], w1v.x, acc[4]);
                    acc[5] = fmaf(xs[j], w1v.y, acc[5]);
                    acc[6] = fmaf(xs[j], w1v.z, acc[6]);
                    acc[7] = fmaf(xs[j], w1v.w, acc[7]);
                }
            }
#pragma unroll
            for (int e = 0; e < 8; e++) {
#pragma unroll
                for (int off = 16; off > 0; off >>= 1)
                    acc[e] += __shfl_xor_sync(0xffffffffu, acc[e], off);
            }
            if (lane == 0) {
#pragma unroll
                for (int e = 0; e < 8; e++) sm_g[wrp >> 1][half][e] = acc[e];
            }
            __syncthreads();
            if (wrp < 4 && lane == 0) {
                const int t2 = p * 4 + wrp;
                float l0 = -INFINITY, l1 = -INFINITY;
                int i0 = 0, i1 = 0;
#pragma unroll
                for (int e = 0; e < 8; e++) {
                    float v = sm_g[wrp][0][e] + sm_g[wrp][1][e];
                    if (v > l0) { l1 = l0; i1 = i0; l0 = v; i0 = e; }
                    else if (v > l1) { l1 = v; i1 = e; }
                }
                float g0 = 1.f / (1.f + __expf(l1 - l0));
                g_e0[t2] = i0; g_e1[t2] = i1;
                g_g0[t2] = g0; g_g1[t2] = 1.f - g0;
            }
        } else {
            const int gw = p * 8 + wrp;
            const float* rr = W2 + (size_t)gw * D_DIM;
            float s = 0.f;
            for (int k = lane * 4; k < D_DIM; k += 128) {
                float4 vv = *(const float4*)(rr + k);
                s += (vv.x + vv.y) + (vv.z + vv.w);
            }
#pragma unroll
            for (int off = 16; off > 0; off >>= 1) s += __shfl_xor_sync(0xffffffffu, s, off);
            if (lane == 0) g_w2sum[gw] = s;
        }
    } else if (bid < G_MAIN + G_INIT) {
        int i = (bid - G_MAIN) * 256 + tid;
        g_src[i] = -1;
        g_rowsum[i] = 0.f;
    } else {
        if (wrp < 8) {
            float s = 0.f;
            for (int k = lane; k < D_DIM; k += 32) s += b2[(size_t)wrp * D_DIM + k];
#pragma unroll
            for (int off = 16; off > 0; off >>= 1) s += __shfl_xor_sync(0xffffffffu, s, off);
            if (lane == 0) g_b2sum[wrp] = s;
        }
    }
}

// ================= K2: dispatch scan (1024 threads) =================
__global__ void __launch_bounds__(1024) k_scan() {
    __shared__ int wT0[32][8], wT1[32][8];
    __shared__ int wOff0[32][8], wOff1[32][8];
    __shared__ int shTot[8];
    const int tid = threadIdx.x, lane = tid & 31, w = tid >> 5;
    const int base = tid * 8;

    int4 a0 = *(const int4*)&g_e0[base];
    int4 a1 = *(const int4*)&g_e0[base + 4];
    int4 c0 = *(const int4*)&g_e1[base];
    int4 c1 = *(const int4*)&g_e1[base + 4];
    const int e0s[8] = {a0.x, a0.y, a0.z, a0.w, a1.x, a1.y, a1.z, a1.w};
    const int e1s[8] = {c0.x, c0.y, c0.z, c0.w, c1.x, c1.y, c1.z, c1.w};

    int cnt0[8], cnt1[8];
#pragma unroll
    for (int e = 0; e < 8; e++) { cnt0[e] = 0; cnt1[e] = 0; }
#pragma unroll
    for (int i = 0; i < 8; i++) { cnt0[e0s[i]]++; cnt1[e1s[i]]++; }

    int inc0[8], inc1[8];
#pragma unroll
    for (int e = 0; e < 8; e++) { inc0[e] = cnt0[e]; inc1[e] = cnt1[e]; }
#pragma unroll
    for (int off = 1; off < 32; off <<= 1) {
#pragma unroll
        for (int e = 0; e < 8; e++) {
            int v0 = __shfl_up_sync(0xffffffffu, inc0[e], off);
            int v1 = __shfl_up_sync(0xffffffffu, inc1[e], off);
            if (lane >= off) { inc0[e] += v0; inc1[e] += v1; }
        }
    }
    if (lane == 31) {
#pragma unroll
        for (int e = 0; e < 8; e++) { wT0[w][e] = inc0[e]; wT1[w][e] = inc1[e]; }
    }
    __syncthreads();
    if (w == 0) {
        int t0[8], t1[8], i0[8], i1[8];
#pragma unroll
        for (int e = 0; e < 8; e++) {
            t0[e] = wT0[lane][e]; t1[e] = wT1[lane][e];
            i0[e] = t0[e]; i1[e] = t1[e];
        }
#pragma unroll
        for (int off = 1; off < 32; off <<= 1) {
#pragma unroll
            for (int e = 0; e < 8; e++) {
                int v0 = __shfl_up_sync(0xffffffffu, i0[e], off);
                int v1 = __shfl_up_sync(0xffffffffu, i1[e], off);
                if (lane >= off) { i0[e] += v0; i1[e] += v1; }
            }
        }
#pragma unroll
        for (int e = 0; e < 8; e++) {
            wOff0[lane][e] = i0[e] - t0[e];
            wOff1[lane][e] = i1[e] - t1[e];
        }
        if (lane == 31) {
#pragma unroll
            for (int e = 0; e < 8; e++) shTot[e] = i0[e];
        }
    }
    __syncthreads();

    int run0[8], run1[8];
#pragma unroll
    for (int e = 0; e < 8; e++) {
        run0[e] = wOff0[w][e] + inc0[e] - cnt0[e];
        run1[e] = shTot[e] + wOff1[w][e] + inc1[e] - cnt1[e];
    }
#pragma unroll
    for (int i = 0; i < 8; i++) {
        int tok = base + i;
        int e = e0s[i];
        int pos = run0[e]++;
        if (pos < C_CAP) { g_p0[tok] = pos; g_src[e * C_CAP + pos] = tok; }
        else             { g_p0[tok] = -1; }
    }
#pragma unroll
    for (int i = 0; i < 8; i++) {
        int tok = base + i;
        int e = e1s[i];
        int pos = run1[e]++;
        if (pos < C_CAP) { g_p1[tok] = pos; g_src[e * C_CAP + pos] = tok; }
        else             { g_p1[tok] = -1; }
    }
}

// ================= K3: HMMA fused expert GEMM + relu*w2sum epilogue =================
// Tile M=128 x N=256, BK=32, NOW 16 warps (4 wm x 4 wn, warp tile 32x64) for 2x occupancy.
#define STRIDE 80
#define OFF_A  0
#define OFF_B  10240
#define STAGE_SZ 30720
#define NSTAGE 4
#define OFF_W2 (STAGE_SZ * NSTAGE)
#define OFF_B1 (OFF_W2 + 1024)
#define SMEM_FFN (OFF_B1 + 1024)
#define NIT (D_DIM / 32)

__global__ void __launch_bounds__(512, 1) k_ffn(const float* __restrict__ b1) {
    extern __shared__ char smem[];
    const uint32_t sbase = smem_u32(smem);
    const int tid = threadIdx.x;
    const int lane = tid & 31, wid = tid >> 5;
    const int wm = wid >> 2, wn = wid & 3;          // 4x4 warps
    const int e = blockIdx.z;
    const int row0 = blockIdx.y * 128;
    const int col0 = blockIdx.x * 256;

    float* sW2 = (float*)(smem + OFF_W2);
    float* sB1 = (float*)(smem + OFF_B1);
    if (tid < 256) {
        sW2[tid] = g_w2sum[e * H_DIM + col0 + tid];
        sB1[tid] = b1[(size_t)e * H_DIM + col0 + tid];
    }

    // ---- loaders: 512 threads. A: 1 slot (16B) each; B: 2 slots (16B) each ----
    const int arow = tid >> 2;                 // 0..127
    const int aoff = tid & 3;                  // 16B slot within 64B row
    const int srcTok = g_src[e * C_CAP + row0 + arow];
    const int aPred = (srcTok >= 0) ? 16 : 0;
    const __half* aPtr = g_xh + (size_t)(srcTok >= 0 ? srcTok : 0) * D_DIM + aoff * 8;
    const int aByte = arow * STRIDE + aoff * 16;

    const int bs0 = tid, bs1 = tid + 512;      // two of 1024 16B slots
    const int brow0 = bs0 >> 2, boff0 = bs0 & 3;
    const int brow1 = bs1 >> 2, boff1 = bs1 & 3;
    const __half* bPtr0 = g_w1h + (size_t)(e * H_DIM + col0 + brow0) * D_DIM + boff0 * 8;
    const __half* bPtr1 = g_w1h + (size_t)(e * H_DIM + col0 + brow1) * D_DIM + boff1 * 8;
    const int bByte0 = brow0 * STRIDE + boff0 * 16;
    const int bByte1 = brow1 * STRIDE + boff1 * 16;

    float acc[2][8][4];
#pragma unroll
    for (int i = 0; i < 2; i++)
#pragma unroll
        for (int j = 0; j < 8; j++)
#pragma unroll
            for (int q = 0; q < 4; q++) acc[i][j][q] = 0.f;

    auto issue = [&](int it, int st) {
        const uint32_t sb = sbase + st * STAGE_SZ;
        const int co = it * 32;
        CP16Z(sb + OFF_A + aByte, aPtr + co, aPred);
        CP16(sb + OFF_B + bByte0, bPtr0 + co);
        CP16(sb + OFF_B + bByte1, bPtr1 + co);
    };

    issue(0, 0); CP_COMMIT();
    issue(1, 1); CP_COMMIT();
    issue(2, 2); CP_COMMIT();

    const uint32_t aFragOff = (wm * 32 + (lane & 15)) * STRIDE + ((lane >> 4) << 4);
    const uint32_t bFragOff = (wn * 64 + (lane & 15)) * STRIDE + ((lane >> 4) << 4);
    uint32_t aStage[NSTAGE], bStage[NSTAGE];
#pragma unroll
    for (int s = 0; s < NSTAGE; s++) {
        aStage[s] = sbase + s * STAGE_SZ + OFF_A + aFragOff;
        bStage[s] = sbase + s * STAGE_SZ + OFF_B + bFragOff;
    }

    for (int it4 = 0; it4 < NIT / 4; it4++) {
#pragma unroll
        for (int s = 0; s < 4; s++) {
            const int it = it4 * 4 + s;
            CP_WAIT2();
            __syncthreads();
            if (it + 3 < NIT) issue(it + 3, (s + 3) & 3);
            CP_COMMIT();

            const uint32_t aB = aStage[s];
            const uint32_t bB = bStage[s];
#pragma unroll
            for (int kh = 0; kh < 2; kh++) {
                uint32_t a[2][4];
#pragma unroll
                for (int ma = 0; ma < 2; ma++)
                    LDM4(a[ma], aB + ma * (16 * STRIDE) + kh * 32);
#pragma unroll
                for (int np = 0; np < 4; np++) {
                    uint32_t tr[4];
                    LDM4(tr, bB + np * (16 * STRIDE) + kh * 32);
#pragma unroll
                    for (int ma = 0; ma < 2; ma++) {
                        MMA2(acc[ma][np * 2],     a[ma], tr[0], tr[2]);
                        MMA2(acc[ma][np * 2 + 1], a[ma], tr[1], tr[3]);
                    }
                }
            }
        }
    }

    // ---- epilogue: relu(z + b1) * w2sum, reduce over N, one atomic per row ----
#pragma unroll
    for (int ma = 0; ma < 2; ma++) {
        float s0 = 0.f, s1 = 0.f;
#pragma unroll
        for (int na = 0; na < 8; na++) {
            int cb = wn * 64 + na * 8 + (lane & 3) * 2;
            float w0 = sW2[cb], w1v = sW2[cb + 1];
            float bb0 = sB1[cb], bb1 = sB1[cb + 1];
            s0 += fmaxf(acc[ma][na][0] + bb0, 0.f) * w0
                + fmaxf(acc[ma][na][1] + bb1, 0.f) * w1v;
            s1 += fmaxf(acc[ma][na][2] + bb0, 0.f) * w0
                + fmaxf(acc[ma][na][3] + bb1, 0.f) * w1v;
        }
        s0 += __shfl_xor_sync(0xffffffffu, s0, 1);
        s0 += __shfl_xor_sync(0xffffffffu, s0, 2);
        s1 += __shfl_xor_sync(0xffffffffu, s1, 1);
        s1 += __shfl_xor_sync(0xffffffffu, s1, 2);
        if ((lane & 3) == 0) {
            int r = row0 + wm * 32 + ma * 16 + (lane >> 2);
            atomicAdd(&g_rowsum[e * C_CAP + r], s0);
            atomicAdd(&g_rowsum[e * C_CAP + r + 8], s1);
        }
    }
}

// ================= K4: fused combine + log_softmax (1024 threads) =================
__global__ void __launch_bounds__(1024) k_out(float* __restrict__ out) {
    __shared__ float sy[S_SEQ];
    __shared__ float red[1024];
    const int b = blockIdx.x, tid = threadIdx.x;

    for (int s = tid; s < S_SEQ; s += 1024) {
        int t = b * S_SEQ + s;
        float y = 0.f;
        int p0 = g_p0[t];
        if (p0 >= 0) {
            int e = g_e0[t];
            y += g_g0[t] * (g_rowsum[e * C_CAP + p0] + g_b2sum[e]);
        }
        int p1 = g_p1[t];
        if (p1 >= 0) {
            int e = g_e1[t];
            y += g_g1[t] * (g_rowsum[e * C_CAP + p1] + g_b2sum[e]);
        }
        sy[s] = y;
    }
    __syncthreads();

    float m = fmaxf(sy[tid], sy[tid + 1024]);
    red[tid] = m; __syncthreads();
    for (int off = 512; off > 0; off >>= 1) {
        if (tid < off) red[tid] = fmaxf(red[tid], red[tid + off]);
        __syncthreads();
    }
    m = red[0]; __syncthreads();

    float sum = expf(sy[tid] - m) + expf(sy[tid + 1024] - m);
    red[tid] = sum; __syncthreads();
    for (int off = 512; off > 0; off >>= 1) {
        if (tid < off) red[tid] += red[tid + off];
        __syncthreads();
    }
    float lse = m + logf(red[0]);

    out[(size_t)b * S_SEQ + tid] = sy[tid] - lse;
    out[(size_t)b * S_SEQ + tid + 1024] = sy[tid + 1024] - lse;
}

// ---------------- launch ----------------
extern "C" void kernel_launch(void* const* d_in, const int* in_sizes, int n_in,
                              void* d_out, int out_size) {
    const float* x  = (const float*)d_in[0];
    const float* Wg = (const float*)d_in[1];
    const float* W1 = (const float*)d_in[2];
    const float* b1 = (const float*)d_in[3];
    const float* W2 = (const float*)d_in[4];
    const float* b2 = (const float*)d_in[5];
    float* out = (float*)d_out;

    cudaFuncSetAttribute(k_ffn, cudaFuncAttributeMaxDynamicSharedMemorySize, SMEM_FFN);

    k_prep<<<G_PREP, 256>>>(x, Wg, W1, W2, b2);
    k_scan<<<1, 1024>>>();
    k_ffn<<<dim3(H_DIM / 256, C_CAP / 128, E_EXP), 512, SMEM_FFN>>>(b1);
    k_out<<<B_BATCH, 1024>>>(out);
}